// round 7
// baseline (speedup 1.0000x reference)
#include <cuda_runtime.h>
#include <cuda_bf16.h>

// Problem: N = 50000 nodes, F = 2048 features, OUT = 256 outputs
//   v[i]   = sum_n adj[n] * fm[n, i]           (column-weighted sum, 409.6 MB read)
//   out[j] = sum_i (A[i] * v[i]) * B[i, j]     (tiny GEMV, ~2 MB)
// Round 6: colsum ~66.5us (6.2 TB/s), gemv 5.2us latency-bound + launch gap.
// Round 7: single fused persistent kernel. 296 CTAs (exactly 2/SM, all
// co-resident) -> legal grid-wide spin barrier; GEMV epilogue runs in-kernel
// on blocks 0..127 with all 512 threads. Deletes one launch + gemv latency.

#define F_DIM 2048
#define OUT_DIM 256

#define P1_THREADS 512            // thread t owns columns [4t, 4t+4) as float4
#define P1_BLOCKS 296             // 2 CTAs/SM * 148 SMs (occ 2 -> 64 regs/thread)

#define EPI_BLOCKS 128
#define EPI_ROWS (F_DIM / EPI_BLOCKS)   // 16 i-rows per epilogue block

// Zero at module load; the kernel restores all of it before exiting, so every
// graph replay sees identical initial state.
__device__ float g_v[F_DIM];
__device__ int   g_arrive;
__device__ int   g_done;

// Streaming 16B load (read-once data: evict-first, keep L2 clean).
__device__ __forceinline__ float4 ldcs4(const float4* p) {
    float4 v;
    asm volatile("ld.global.cs.v4.f32 {%0,%1,%2,%3}, [%4];"
                 : "=f"(v.x), "=f"(v.y), "=f"(v.z), "=f"(v.w) : "l"(p));
    return v;
}

__global__ __launch_bounds__(P1_THREADS, 2)
void fused_kernel(const float* __restrict__ adj,
                  const float* __restrict__ fm,
                  const float* __restrict__ A,
                  const float* __restrict__ B,
                  int n_rows, float* __restrict__ out) {
    const int t = threadIdx.x;                       // 0..511
    const int b = blockIdx.x;                        // 0..295

    if (b == 0 && t < OUT_DIM) out[t] = 0.0f;        // harness poisons d_out

    // ---------------- Phase 1: streaming column-weighted sum ----------------
    const float4* __restrict__ fm4 = (const float4*)fm;
    const size_t rstride = F_DIM / 4;                // float4s per row

    float ax = 0.f, ay = 0.f, az = 0.f, aw = 0.f;

    int r = b;
    for (; r + 7 * P1_BLOCKS < n_rows; r += 8 * P1_BLOCKS) {
        float4 x0 = ldcs4(fm4 + (size_t)(r + 0 * P1_BLOCKS) * rstride + t);
        float4 x1 = ldcs4(fm4 + (size_t)(r + 1 * P1_BLOCKS) * rstride + t);
        float4 x2 = ldcs4(fm4 + (size_t)(r + 2 * P1_BLOCKS) * rstride + t);
        float4 x3 = ldcs4(fm4 + (size_t)(r + 3 * P1_BLOCKS) * rstride + t);
        float4 x4 = ldcs4(fm4 + (size_t)(r + 4 * P1_BLOCKS) * rstride + t);
        float4 x5 = ldcs4(fm4 + (size_t)(r + 5 * P1_BLOCKS) * rstride + t);
        float4 x6 = ldcs4(fm4 + (size_t)(r + 6 * P1_BLOCKS) * rstride + t);
        float4 x7 = ldcs4(fm4 + (size_t)(r + 7 * P1_BLOCKS) * rstride + t);
        float a0 = __ldg(adj + r + 0 * P1_BLOCKS);
        float a1 = __ldg(adj + r + 1 * P1_BLOCKS);
        float a2 = __ldg(adj + r + 2 * P1_BLOCKS);
        float a3 = __ldg(adj + r + 3 * P1_BLOCKS);
        float a4 = __ldg(adj + r + 4 * P1_BLOCKS);
        float a5 = __ldg(adj + r + 5 * P1_BLOCKS);
        float a6 = __ldg(adj + r + 6 * P1_BLOCKS);
        float a7 = __ldg(adj + r + 7 * P1_BLOCKS);
        ax = fmaf(a0, x0.x, ax); ay = fmaf(a0, x0.y, ay);
        az = fmaf(a0, x0.z, az); aw = fmaf(a0, x0.w, aw);
        ax = fmaf(a1, x1.x, ax); ay = fmaf(a1, x1.y, ay);
        az = fmaf(a1, x1.z, az); aw = fmaf(a1, x1.w, aw);
        ax = fmaf(a2, x2.x, ax); ay = fmaf(a2, x2.y, ay);
        az = fmaf(a2, x2.z, az); aw = fmaf(a2, x2.w, aw);
        ax = fmaf(a3, x3.x, ax); ay = fmaf(a3, x3.y, ay);
        az = fmaf(a3, x3.z, az); aw = fmaf(a3, x3.w, aw);
        ax = fmaf(a4, x4.x, ax); ay = fmaf(a4, x4.y, ay);
        az = fmaf(a4, x4.z, az); aw = fmaf(a4, x4.w, aw);
        ax = fmaf(a5, x5.x, ax); ay = fmaf(a5, x5.y, ay);
        az = fmaf(a5, x5.z, az); aw = fmaf(a5, x5.w, aw);
        ax = fmaf(a6, x6.x, ax); ay = fmaf(a6, x6.y, ay);
        az = fmaf(a6, x6.z, az); aw = fmaf(a6, x6.w, aw);
        ax = fmaf(a7, x7.x, ax); ay = fmaf(a7, x7.y, ay);
        az = fmaf(a7, x7.z, az); aw = fmaf(a7, x7.w, aw);
    }
    for (; r < n_rows; r += P1_BLOCKS) {
        float a = __ldg(adj + r);
        float4 x = ldcs4(fm4 + (size_t)r * rstride + t);
        ax = fmaf(a, x.x, ax); ay = fmaf(a, x.y, ay);
        az = fmaf(a, x.z, az); aw = fmaf(a, x.w, aw);
    }

    atomicAdd(&g_v[4 * t + 0], ax);
    atomicAdd(&g_v[4 * t + 1], ay);
    atomicAdd(&g_v[4 * t + 2], az);
    atomicAdd(&g_v[4 * t + 3], aw);

    // ---------------- Grid-wide barrier (all 296 CTAs co-resident) ----------
    __syncthreads();                 // all atomics of this CTA issued
    if (t == 0) {
        __threadfence();             // release: g_v updates visible
        atomicAdd(&g_arrive, 1);
        while (*(volatile int*)&g_arrive < P1_BLOCKS) { }
        __threadfence();             // acquire: see everyone's g_v updates
    }
    __syncthreads();

    // ---------------- Phase 2: GEMV epilogue on blocks 0..127 ---------------
    if (b < EPI_BLOCKS) {
        __shared__ float av[EPI_ROWS];
        const int i0 = b * EPI_ROWS;
        if (t < EPI_ROWS) {
            int i = i0 + t;
            av[t] = A[i] * g_v[i];
            g_v[i] = 0.0f;                           // restore for next replay
        }
        __syncthreads();

        // Two 256-thread j-groups, each covering 8 of the 16 i-rows.
        const int j = t & 255;
        const int h = t >> 8;                        // 0 or 1
        const int k0 = h * 8;
        float s0 = 0.f, s1 = 0.f, s2 = 0.f, s3 = 0.f;
#pragma unroll
        for (int k = 0; k < 8; k += 4) {
            size_t base = (size_t)(i0 + k0 + k) * OUT_DIM + j;
            s0 = fmaf(av[k0 + k + 0], __ldg(B + base + 0 * OUT_DIM), s0);
            s1 = fmaf(av[k0 + k + 1], __ldg(B + base + 1 * OUT_DIM), s1);
            s2 = fmaf(av[k0 + k + 2], __ldg(B + base + 2 * OUT_DIM), s2);
            s3 = fmaf(av[k0 + k + 3], __ldg(B + base + 3 * OUT_DIM), s3);
        }
        atomicAdd(&out[j], (s0 + s1) + (s2 + s3));
    }

    // ---------------- Reset counters for graph replay ----------------------
    if (t == 0) {
        int d = atomicAdd(&g_done, 1);
        if (d == P1_BLOCKS - 1) {                    // last CTA out
            g_arrive = 0;
            __threadfence();
            g_done = 0;
        }
    }
}

// ---------------------------------------------------------------------------
// Launch. Inputs (metadata order): node_adjacency [1,50000], feature_map
// [50000,2048], A [2048,1], B [2048,256], fe_mask_rate (scalar == 0, ignored).
// Output: float32 [1,256].
// ---------------------------------------------------------------------------
extern "C" void kernel_launch(void* const* d_in, const int* in_sizes, int n_in,
                              void* d_out, int out_size) {
    const float* adj = (const float*)d_in[0];
    const float* fm  = (const float*)d_in[1];
    const float* A   = (const float*)d_in[2];
    const float* B   = (const float*)d_in[3];
    float* out = (float*)d_out;

    const int n_rows = in_sizes[0];                  // 50000

    fused_kernel<<<P1_BLOCKS, P1_THREADS>>>(adj, fm, A, B, n_rows, out);
}